// round 12
// baseline (speedup 1.0000x reference)
#include <cuda_runtime.h>
#include <cuda_bf16.h>
#include <cstdint>
#include <cstddef>

#define WTOT  2048
#define CDIM  1024
#define MROWS 4096
#define KWP   1024      /* plane words per K=1024 row: hi 512 | lo 512 */

// ---------------- scratch (no allocation allowed) ----------------
__device__ __align__(256) uint32_t g_xa[(size_t)MROWS * KWP];        // x planes
__device__ __align__(256) uint32_t g_wpb[(size_t)2048 * KWP];        // W_proj planes
__device__ __align__(256) uint32_t g_wob[(size_t)1024 * KWP];        // W_out planes
__device__ __align__(256) uint32_t g_na[(size_t)MROWS * KWP];        // nudged planes
__device__ __align__(256) uint32_t g_qk[(size_t)32 * 2048 * 64];     // Q/K unified planes
__device__ __align__(256) uint32_t g_vnh[(size_t)32 * 2048 * 32];    // V n-major hi (bf16x2)
__device__ __align__(256) uint32_t g_vnl[(size_t)32 * 2048 * 32];    // V n-major lo
__device__ __align__(256) uint32_t g_vth[(size_t)32 * 64 * 1024];    // V^T hi plane
__device__ __align__(256) uint32_t g_vtl[(size_t)32 * 64 * 1024];    // V^T lo plane

// ---------------- helpers ----------------
__device__ __forceinline__ uint32_t smem_u32(const void* p) {
    uint32_t a;
    asm("{ .reg .u64 t; cvta.to.shared.u64 t, %1; cvt.u32.u64 %0, t; }" : "=r"(a) : "l"(p));
    return a;
}
// split two floats into (hi pair, lo pair) bf16x2 words
__device__ __forceinline__ void split_pair(float a, float b, uint32_t& hi, uint32_t& lo) {
    __nv_bfloat16 ah = __float2bfloat16_rn(a), bh = __float2bfloat16_rn(b);
    float af = __bfloat162float(ah), bf = __bfloat162float(bh);
    __nv_bfloat16 al = __float2bfloat16_rn(a - af), bl = __float2bfloat16_rn(b - bf);
    hi = (uint32_t)__bfloat16_as_ushort(ah) | ((uint32_t)__bfloat16_as_ushort(bh) << 16);
    lo = (uint32_t)__bfloat16_as_ushort(al) | ((uint32_t)__bfloat16_as_ushort(bl) << 16);
}
__device__ __forceinline__ void mma16816(float* d, const uint32_t* a, const uint32_t* b) {
    asm("mma.sync.aligned.m16n8k16.row.col.f32.bf16.bf16.f32 "
        "{%0,%1,%2,%3}, {%4,%5,%6,%7}, {%8,%9}, {%0,%1,%2,%3};"
        : "+f"(d[0]), "+f"(d[1]), "+f"(d[2]), "+f"(d[3])
        : "r"(a[0]), "r"(a[1]), "r"(a[2]), "r"(a[3]), "r"(b[0]), "r"(b[1]));
}
__device__ __forceinline__ void ldsm_x4(uint32_t* r, uint32_t addr) {
    asm volatile("ldmatrix.sync.aligned.m8n8.x4.shared.b16 {%0,%1,%2,%3}, [%4];"
        : "=r"(r[0]), "=r"(r[1]), "=r"(r[2]), "=r"(r[3]) : "r"(addr));
}
__device__ __forceinline__ void cp16(uint32_t dst, const void* src) {
    asm volatile("cp.async.cg.shared.global [%0], [%1], 16;" :: "r"(dst), "l"(src) : "memory");
}
#define CP_COMMIT() asm volatile("cp.async.commit_group;" ::: "memory")
#define CP_WAIT(n)  asm volatile("cp.async.wait_group %0;" :: "n"(n) : "memory")

// ---------------- one fused one-time plane-split kernel ----------------
#define NTASK_X  (MROWS * 512)
#define NTASK_WP (2048 * 512)
#define NTASK_WO (1024 * 512)
__global__ void pack_all(const float* __restrict__ x, const float* __restrict__ Wp,
                         const float* __restrict__ Wo,
                         uint32_t* __restrict__ xa, uint32_t* __restrict__ wpb,
                         uint32_t* __restrict__ wob) {
    int idx = blockIdx.x * 256 + threadIdx.x;
    const float* src; uint32_t* dst;
    if (idx < NTASK_X)                 { src = x;  dst = xa; }
    else if (idx < NTASK_X + NTASK_WP) { src = Wp; dst = wpb; idx -= NTASK_X; }
    else if (idx < NTASK_X + NTASK_WP + NTASK_WO)
                                       { src = Wo; dst = wob; idx -= NTASK_X + NTASK_WP; }
    else return;
    int row = idx >> 9, kp = idx & 511;
    float2 v = *(const float2*)(src + (size_t)row * 1024 + 2 * kp);
    uint32_t hi, lo;
    split_pair(v.x, v.y, hi, lo);
    dst[(size_t)row * KWP + kp] = hi;
    dst[(size_t)row * KWP + 512 + kp] = lo;
}

// V bf16 transpose: [bh][w][n] planes -> [bh][n][s/2 pair] planes
__global__ __launch_bounds__(256) void vt_pack2(const uint32_t* __restrict__ vnh,
                                                const uint32_t* __restrict__ vnl,
                                                uint32_t* __restrict__ vth,
                                                uint32_t* __restrict__ vtl) {
    __shared__ unsigned short sh[128][66];
    __shared__ unsigned short sl[128][66];
    const int tid = threadIdx.x;
    const int wc = blockIdx.x, bh = blockIdx.y;
    const int w0 = wc * 128;
    const size_t base = ((size_t)bh * 2048 + w0) * 32;
#pragma unroll
    for (int i = 0; i < 16; i++) {
        int idx = i * 256 + tid, w = idx >> 5, np = idx & 31;
        uint32_t hw = vnh[base + (size_t)w * 32 + np];
        uint32_t lw = vnl[base + (size_t)w * 32 + np];
        sh[w][2 * np] = (unsigned short)(hw & 0xffff);
        sh[w][2 * np + 1] = (unsigned short)(hw >> 16);
        sl[w][2 * np] = (unsigned short)(lw & 0xffff);
        sl[w][2 * np + 1] = (unsigned short)(lw >> 16);
    }
    __syncthreads();
#pragma unroll
    for (int i = 0; i < 16; i++) {
        int task = i * 256 + tid;
        int n = task >> 6, wp = task & 63;
        uint32_t hi = (uint32_t)sh[2 * wp][n] | ((uint32_t)sh[2 * wp + 1][n] << 16);
        uint32_t lo = (uint32_t)sl[2 * wp][n] | ((uint32_t)sl[2 * wp + 1][n] << 16);
        size_t o = ((size_t)bh * 64 + n) * 1024 + (w0 >> 1) + wp;
        vth[o] = hi; vtl[o] = lo;
    }
}

// ---------------- GEMM on planes: chunk-32 fp32, 3-stage, 1 barrier/chunk -----
// smem row per chunk: [hi 16 words | lo 16 words] + 4 pad, stride 36.
#define STRG 36
#define NCHG 32
#define NSTG 3
#define ATW  (128 * STRG)           /* 4608 words per operand per stage */
#define BUFW (2 * ATW)              /* 9216 */
#define GSMEMB (NSTG * BUFW * 4)    /* 110592 B */

__global__ __launch_bounds__(256, 2) void gemm_pl(
    const uint32_t* __restrict__ Ap, const uint32_t* __restrict__ Bp,
    float* __restrict__ C, int N, int mode,
    uint32_t* __restrict__ qk,
    uint32_t* __restrict__ vnh, uint32_t* __restrict__ vnl)
{
    extern __shared__ uint32_t sw[];
    const uint32_t sbase = smem_u32(sw);
    const int tid = threadIdx.x, lane = tid & 31, wid = tid >> 5;
    const int g = lane >> 2, t = lane & 3, rowInM = lane & 7, j = lane >> 3;
    const int m0 = blockIdx.y * 128, n0 = blockIdx.x * 128;
    const int wm = wid >> 2, wn = wid & 3;

    const uint32_t* Arow = Ap + (size_t)m0 * KWP;
    const uint32_t* Brow = Bp + (size_t)n0 * KWP;

    // per chunk c: hi words c*16..+15, lo words 512+c*16..+15
#define GISSUE(c_, st_) do { \
    uint32_t dA_ = sbase + (st_) * BUFW * 4; \
    uint32_t dB_ = dA_ + ATW * 4; \
    _Pragma("unroll") \
    for (int i_ = 0; i_ < 4; i_++) { \
        int idx_ = i_ * 256 + tid, row_ = idx_ >> 3, q_ = idx_ & 7; \
        int so_ = (q_ < 4) ? ((c_) * 16 + q_ * 4) : (512 + (c_) * 16 + (q_ - 4) * 4); \
        cp16(dA_ + (row_ * STRG + q_ * 4) * 4, Arow + (size_t)row_ * KWP + so_); \
    } \
    _Pragma("unroll") \
    for (int i_ = 0; i_ < 4; i_++) { \
        int idx_ = i_ * 256 + tid, row_ = idx_ >> 3, q_ = idx_ & 7; \
        int so_ = (q_ < 4) ? ((c_) * 16 + q_ * 4) : (512 + (c_) * 16 + (q_ - 4) * 4); \
        cp16(dB_ + (row_ * STRG + q_ * 4) * 4, Brow + (size_t)row_ * KWP + so_); \
    } \
    CP_COMMIT(); } while (0)

    GISSUE(0, 0);
    GISSUE(1, 1);

    float acc[4][4][4] = {};
    int st = 0;                         // stage of chunk c

    for (int c = 0; c < NCHG; c++) {
        if (c + 1 < NCHG) CP_WAIT(1);   // chunk c done; c+1 may still fly
        else              CP_WAIT(0);
        __syncthreads();                // publish c; stage of (c-1) is free
        if (c + 2 < NCHG) {
            int st2 = st + 2; if (st2 >= NSTG) st2 -= NSTG;
            GISSUE(c + 2, st2);
        }

        const uint32_t abase = sbase + st * BUFW * 4;
        const uint32_t bbase = abase + ATW * 4;
#pragma unroll
        for (int s4 = 0; s4 < 2; s4++) {      // k16 steps in chunk
            uint32_t ah[4][4], bh2[2][4], bl2[2][4];
#pragma unroll
            for (int mf = 0; mf < 4; mf++)
                ldsm_x4(ah[mf], abase + ((wm * 64 + mf * 16 + rowInM + 8 * (j & 1)) * STRG
                                          + s4 * 8 + 4 * (j >> 1)) * 4);
#pragma unroll
            for (int p = 0; p < 2; p++) {
                uint32_t brow = (wn * 32 + p * 16 + (j >> 1) * 8 + rowInM) * STRG
                                + s4 * 8 + 4 * (j & 1);
                ldsm_x4(bh2[p], bbase + brow * 4);
                ldsm_x4(bl2[p], bbase + (brow + 16) * 4);
            }
#pragma unroll
            for (int mf = 0; mf < 4; mf++)
#pragma unroll
                for (int nf = 0; nf < 4; nf++) {
                    const uint32_t* bhf = &bh2[nf >> 1][(nf & 1) * 2];
                    const uint32_t* blf = &bl2[nf >> 1][(nf & 1) * 2];
                    mma16816(acc[mf][nf], ah[mf], bhf);
                    mma16816(acc[mf][nf], ah[mf], blf);
                }
            uint32_t al[4][4];
#pragma unroll
            for (int mf = 0; mf < 4; mf++)
                ldsm_x4(al[mf], abase + ((wm * 64 + mf * 16 + rowInM + 8 * (j & 1)) * STRG
                                          + 16 + s4 * 8 + 4 * (j >> 1)) * 4);
#pragma unroll
            for (int mf = 0; mf < 4; mf++)
#pragma unroll
                for (int nf = 0; nf < 4; nf++)
                    mma16816(acc[mf][nf], al[mf], &bh2[nf >> 1][(nf & 1) * 2]);
        }
        if (++st >= NSTG) st = 0;
    }

    // ---- epilogue ----
    if (mode == 0) {
#pragma unroll
        for (int mf = 0; mf < 4; mf++)
#pragma unroll
            for (int nf = 0; nf < 4; nf++) {
                int r = m0 + wm * 64 + mf * 16 + g;
                int cc = n0 + wn * 32 + nf * 8 + 2 * t;
                *(float2*)(C + (size_t)r * N + cc) =
                    make_float2(acc[mf][nf][0], acc[mf][nf][1]);
                *(float2*)(C + (size_t)(r + 8) * N + cc) =
                    make_float2(acc[mf][nf][2], acc[mf][nf][3]);
            }
    } else {
        // GEMM1: cols [0,1024) -> unified Q/K planes; cols [1024,2048) -> V n-major planes
#pragma unroll
        for (int mf = 0; mf < 4; mf++)
#pragma unroll
            for (int nf = 0; nf < 4; nf++) {
                int r1 = m0 + wm * 64 + mf * 16 + g;
                int cc = n0 + wn * 32 + nf * 8 + 2 * t;
                if (cc < 1024) {
                    int hh = cc >> 6, kc = cc & 63;
#pragma unroll
                    for (int half = 0; half < 2; half++) {
                        int r = r1 + 8 * half;
                        int bb = r >> 11, w = r & 2047;
                        uint32_t* rowp = qk + ((size_t)(bb * 16 + hh) * 2048 + w) * 64;
                        uint32_t hi, lo;
                        split_pair(acc[mf][nf][2 * half], acc[mf][nf][2 * half + 1], hi, lo);
                        rowp[(kc >> 1)] = hi;
                        rowp[32 + (kc >> 1)] = lo;
                    }
                } else {
                    int cv = cc - 1024;
                    int hh = cv >> 6, n = cv & 63;
#pragma unroll
                    for (int half = 0; half < 2; half++) {
                        int r = r1 + 8 * half;
                        int bb = r >> 11, w = r & 2047;
                        uint32_t hi, lo;
                        split_pair(acc[mf][nf][2 * half], acc[mf][nf][2 * half + 1], hi, lo);
                        size_t o = ((size_t)(bb * 16 + hh) * 2048 + w) * 32 + (n >> 1);
                        vnh[o] = hi; vnl[o] = lo;
                    }
                }
            }
    }
#undef GISSUE
}

// ---------------- fused causal attention on unified Q/K planes (R11) ----------
// CTA = 64 q rows, 128 threads, 2 CTAs/SM. Row = 64 words [hi32|lo32], stride 68.
#define STRA    68
#define QTW     (64 * STRA)            /* 4352 */
#define KBW     (64 * STRA)
#define VPLANEB 9216                   /* 64 rows * 144 B */
#define VBUFB   (2 * VPLANEB)
#define VBASEB  ((QTW + 2 * KBW) * 4)  /* 52224 */
#define ASMEMB  (VBASEB + 2 * VBUFB)   /* 89088 B */

__global__ __launch_bounds__(128, 2) void attn_pl(
    const uint32_t* __restrict__ qk,
    const uint32_t* __restrict__ vth, const uint32_t* __restrict__ vtl,
    uint32_t* __restrict__ na)
{
    extern __shared__ uint32_t sw[];
    const uint32_t sbase = smem_u32(sw);
    const int tid = threadIdx.x, lane = tid & 31, wid = tid >> 5;
    const int g = lane >> 2, t = lane & 3, rowInM = lane & 7, j = lane >> 3;
    const int qt = 31 - blockIdx.x;           // largest-work tiles first
    const int q0 = qt * 64;
    const int bh = blockIdx.y, b = bh >> 4, h = bh & 15;
    const int wq = wid >> 1, wlo = wid & 1;

    const uint32_t* qkrow = qk + (size_t)bh * 2048 * 64;
    const uint32_t* qrow  = qkrow + (size_t)q0 * 64;
    const uint32_t* vhp = vth + (size_t)bh * 64 * 1024;
    const uint32_t* vlp = vtl + (size_t)bh * 64 * 1024;

#define KVISSUE(sb_, buf_) do { \
    uint32_t kdst_ = sbase + (QTW + (buf_) * KBW) * 4; \
    _Pragma("unroll") \
    for (int i_ = 0; i_ < 8; i_++) { \
        int idx_ = i_ * 128 + tid, row_ = idx_ >> 4, q_ = idx_ & 15; \
        cp16(kdst_ + (row_ * STRA + q_ * 4) * 4, \
             qkrow + (size_t)((sb_) * 64 + row_) * 64 + q_ * 4); \
    } \
    uint32_t vdst_ = sbase + VBASEB + (buf_) * VBUFB; \
    _Pragma("unroll") \
    for (int i_ = 0; i_ < 4; i_++) { \
        int idx_ = i_ * 128 + tid, row_ = idx_ >> 3, q_ = idx_ & 7; \
        cp16(vdst_ + row_ * 144 + q_ * 16, \
             vhp + (size_t)row_ * 1024 + (sb_) * 32 + q_ * 4); \
        cp16(vdst_ + VPLANEB + row_ * 144 + q_ * 16, \
             vlp + (size_t)row_ * 1024 + (sb_) * 32 + q_ * 4); \
    } \
    CP_COMMIT(); } while (0)

    // prologue: Q tile (64 rows x 64 words) + KV block 0
#pragma unroll
    for (int i = 0; i < 8; i++) {
        int idx = i * 128 + tid, row = idx >> 4, q = idx & 15;
        cp16(sbase + (row * STRA + q * 4) * 4, qrow + (size_t)row * 64 + q * 4);
    }
    KVISSUE(0, 0);

    float oacc[2][8][4] = {};
    const int nS = qt + 1;

    for (int sb = 0; sb < nS; sb++) {
        CP_WAIT(0);
        __syncthreads();
        if (sb + 1 < nS) KVISSUE(sb + 1, (sb + 1) & 1);

        const uint32_t kbs = sbase + (QTW + (sb & 1) * KBW) * 4;
        const uint32_t vbs = sbase + VBASEB + (sb & 1) * VBUFB;

        // ---- QK: warp tile 32q x 32s, 4 k16 steps, 3-term planes ----
        float sacc[2][4][4] = {};
#pragma unroll
        for (int s4 = 0; s4 < 4; s4++) {
            uint32_t qh[2][4], ql[2][4], kh2[2][4], kl2[2][4];
#pragma unroll
            for (int mf = 0; mf < 2; mf++) {
                uint32_t arow = (wq * 32 + mf * 16 + rowInM + 8 * (j & 1)) * STRA
                                + s4 * 8 + 4 * (j >> 1);
                ldsm_x4(qh[mf], sbase + arow * 4);
                ldsm_x4(ql[mf], sbase + (arow + 32) * 4);
            }
#pragma unroll
            for (int p = 0; p < 2; p++) {
                uint32_t brow = (wlo * 32 + p * 16 + (j >> 1) * 8 + rowInM) * STRA
                                + s4 * 8 + 4 * (j & 1);
                ldsm_x4(kh2[p], kbs + brow * 4);
                ldsm_x4(kl2[p], kbs + (brow + 32) * 4);
            }
#pragma unroll
            for (int mf = 0; mf < 2; mf++)
#pragma unroll
                for (int nf = 0; nf < 4; nf++) {
                    const uint32_t* khf = &kh2[nf >> 1][(nf & 1) * 2];
                    const uint32_t* klf = &kl2[nf >> 1][(nf & 1) * 2];
                    mma16816(sacc[mf][nf], qh[mf], khf);
                    mma16816(sacc[mf][nf], ql[mf], khf);
                    mma16816(sacc[mf][nf], qh[mf], klf);
                }
        }

        // ---- scale (+ mask only on diagonal-crossing warp blocks) ----
        const int s0w = sb * 64 + wlo * 32;
        const int q0w = q0 + wq * 32;
        if (s0w + 31 <= q0w) {
#pragma unroll
            for (int mf = 0; mf < 2; mf++)
#pragma unroll
                for (int nf = 0; nf < 4; nf++)
#pragma unroll
                    for (int e = 0; e < 4; e++)
                        sacc[mf][nf][e] *= 0.125f;
        } else {
#pragma unroll
            for (int mf = 0; mf < 2; mf++)
#pragma unroll
                for (int nf = 0; nf < 4; nf++)
#pragma unroll
                    for (int e = 0; e < 4; e++) {
                        int sg = s0w + nf * 8 + 2 * t + (e & 1);
                        int qg = q0w + mf * 16 + g + 8 * (e >> 1);
                        sacc[mf][nf][e] = (sg <= qg) ? sacc[mf][nf][e] * 0.125f : 0.f;
                    }
        }

        // ---- SV: A frags from sacc (hi/lo), B from V planes ----
#pragma unroll
        for (int ki = 0; ki < 2; ki++) {
            uint32_t ash[2][4], asl[2][4];
#pragma unroll
            for (int mf = 0; mf < 2; mf++) {
                split_pair(sacc[mf][2 * ki][0],     sacc[mf][2 * ki][1],     ash[mf][0], asl[mf][0]);
                split_pair(sacc[mf][2 * ki][2],     sacc[mf][2 * ki][3],     ash[mf][1], asl[mf][1]);
                split_pair(sacc[mf][2 * ki + 1][0], sacc[mf][2 * ki + 1][1], ash[mf][2], asl[mf][2]);
                split_pair(sacc[mf][2 * ki + 1][2], sacc[mf][2 * ki + 1][3], ash[mf][3], asl[mf][3]);
            }
            uint32_t bh_[4][4], bl_[4][4];
#pragma unroll
            for (int p = 0; p < 4; p++) {
                uint32_t col = wlo * 64 + ki * 32 + (j & 1) * 16;
                uint32_t row = (p * 16 + (j >> 1) * 8 + rowInM) * 144;
                ldsm_x4(bh_[p], vbs + row + col);
                ldsm_x4(bl_[p], vbs + VPLANEB + row + col);
            }
#pragma unroll
            for (int mf = 0; mf < 2; mf++)
#pragma unroll
                for (int nf = 0; nf < 8; nf++) {
                    const uint32_t* bhf = &bh_[nf >> 1][(nf & 1) * 2];
                    const uint32_t* blf = &bl_[nf >> 1][(nf & 1) * 2];
                    mma16816(oacc[mf][nf], ash[mf], bhf);
                    mma16816(oacc[mf][nf], asl[mf], bhf);
                    mma16816(oacc[mf][nf], ash[mf], blf);
                }
        }
    }

    // ---- cross-wlo reduction (scratch over Q area, stride 66) ----
    __syncthreads();
    if (wlo == 1) {
#pragma unroll
        for (int mf = 0; mf < 2; mf++)
#pragma unroll
            for (int nf = 0; nf < 8; nf++)
#pragma unroll
                for (int e = 0; e < 4; e++) {
                    int qloc = mf * 16 + g + 8 * (e >> 1);
                    int n = nf * 8 + 2 * t + (e & 1);
                    sw[wq * 2112 + qloc * 66 + n] = __float_as_uint(oacc[mf][nf][e]);
                }
    }
    __syncthreads();
    if (wlo == 0) {
#pragma unroll
        for (int mf = 0; mf < 2; mf++)
#pragma unroll
            for (int nf = 0; nf < 8; nf++)
#pragma unroll
                for (int half = 0; half < 2; half++) {
                    int qloc = mf * 16 + g + 8 * half;
                    int n = nf * 8 + 2 * t;
                    float sA = oacc[mf][nf][2 * half] +
                               __uint_as_float(sw[wq * 2112 + qloc * 66 + n]);
                    float sB = oacc[mf][nf][2 * half + 1] +
                               __uint_as_float(sw[wq * 2112 + qloc * 66 + n + 1]);
                    int row = q0 + wq * 32 + qloc;
                    int cc = h * 64 + n;
                    uint32_t hi, lo;
                    split_pair(sA, sB, hi, lo);
                    uint32_t* rowp = na + (size_t)(b * 2048 + row) * KWP;
                    rowp[(cc >> 1)] = hi;
                    rowp[512 + (cc >> 1)] = lo;
                }
    }
#undef KVISSUE
}

// ---------------- kernel_launch ----------------
extern "C" void kernel_launch(void* const* d_in, const int* in_sizes, int n_in,
                              void* d_out, int out_size)
{
    const float* x  = (const float*)d_in[0];
    const float* Wp = (const float*)d_in[1];
    const float* Wo = (const float*)d_in[2];
    float* out = (float*)d_out;

    uint32_t *xa, *wpb, *wob, *na, *qk, *vnh, *vnl, *vth, *vtl;
    cudaGetSymbolAddress((void**)&xa,  g_xa);
    cudaGetSymbolAddress((void**)&wpb, g_wpb);
    cudaGetSymbolAddress((void**)&wob, g_wob);
    cudaGetSymbolAddress((void**)&na,  g_na);
    cudaGetSymbolAddress((void**)&qk,  g_qk);
    cudaGetSymbolAddress((void**)&vnh, g_vnh);
    cudaGetSymbolAddress((void**)&vnl, g_vnl);
    cudaGetSymbolAddress((void**)&vth, g_vth);
    cudaGetSymbolAddress((void**)&vtl, g_vtl);

    cudaFuncSetAttribute(gemm_pl, cudaFuncAttributeMaxDynamicSharedMemorySize, GSMEMB);
    cudaFuncSetAttribute(attn_pl, cudaFuncAttributeMaxDynamicSharedMemorySize, ASMEMB);

    {
        int total = NTASK_X + NTASK_WP + NTASK_WO;
        pack_all<<<(total + 255) / 256, 256>>>(x, Wp, Wo, xa, wpb, wob);
    }

    // 1) proj GEMM; epilogue emits unified Q/K planes + V n-major bf16 planes
    gemm_pl<<<dim3(2048 / 128, MROWS / 128), 256, GSMEMB>>>(
        xa, wpb, nullptr, 2048, 1, qk, vnh, vnl);

    // V bf16 transpose -> s-major hi/lo planes
    vt_pack2<<<dim3(WTOT / 128, 32), 256>>>(vnh, vnl, vth, vtl);

    // 2) fused causal attention; epilogue emits nudged planes
    attn_pl<<<dim3(32, 32), 128, ASMEMB>>>(qk, vth, vtl, na);

    // 3) output GEMM -> fp32 out
    gemm_pl<<<dim3(1024 / 128, MROWS / 128), 256, GSMEMB>>>(
        na, wob, out, 1024, 0, nullptr, nullptr, nullptr);
}